// round 9
// baseline (speedup 1.0000x reference)
#include <cuda_runtime.h>

// out = segment_sum(source[src_idx], seg_ids); softmax over singleton axis==1,
// so all attention machinery is dead code.
//
//  A) boundary kernel: seg_ids sorted -> per-node edge range {start,end} into
//     zero-initialized __device__ int2 (idempotent across graph replays; empty
//     nodes stay {0,0}).
//  B) gather kernel: one warp per node. Half-warp per edge: 16 lanes x float4
//     = one 256B source row per LDG.128, so each warp instruction gathers TWO
//     edges. 16 edges per iteration (8 independent LDG.128 in flight). One
//     final predicated iteration handles deg%16 (predicated LDG: no wasted
//     wavefronts, no serial tail). Cross-half shfl reduction, STG.128 store
//     (empty nodes store zeros -> no separate zero kernel, no atomics at all).
//
// Inputs: 0 source[N,64] f32, 2 src_idx[E] i32, 3 seg_ids[E] i32 (sorted).

#define N_NODES_MAX 100000

__device__ int2 g_seg_range[N_NODES_MAX];   // zero-initialized

__global__ void __launch_bounds__(256)
boundary_kernel(const int* __restrict__ seg_ids, int E) {
    int e = blockIdx.x * blockDim.x + threadIdx.x;
    if (e >= E) return;
    int s = seg_ids[e];
    if (e == 0 || seg_ids[e - 1] != s) g_seg_range[s].x = e;
    if (e == E - 1 || seg_ids[e + 1] != s) g_seg_range[s].y = e + 1;
}

__global__ void __launch_bounds__(256)
gather_kernel(const float4* __restrict__ src4,
              const int* __restrict__ src_idx,
              float* __restrict__ out, int N) {
    const int node = blockIdx.x * 8 + (threadIdx.x >> 5);
    if (node >= N) return;
    const int lane    = threadIdx.x & 31;
    const int sub     = lane & 15;            // column group [4*sub, 4*sub+4)
    const int halfsel = lane & 16;            // 0 (edges k) / 16 (edges 8+k)
    const int eoff    = ((lane >> 4) << 3) + (lane & 7);  // 0-7 | 8-15
    const int ebase   = halfsel ? 8 : 0;

    int2 r = __ldg(&g_seg_range[node]);
    int e = r.x;
    const int e1 = r.y;

    float4 acc = make_float4(0.f, 0.f, 0.f, 0.f);

    int nfull = (e1 - e) >> 4;
    for (int q = 0; q < nfull; ++q, e += 16) {
        int my = __ldg(&src_idx[e + eoff]);   // 16 consecutive idx per half
#pragma unroll
        for (int k = 0; k < 8; ++k) {
            int idx = __shfl_sync(0xffffffffu, my, halfsel + k);
            float4 v = __ldg(&src4[(long long)idx * 16 + sub]);
            acc.x += v.x; acc.y += v.y; acc.z += v.z; acc.w += v.w;
        }
    }

    int rem = e1 - e;                          // 0..15
    if (rem > 0) {
        int my = __ldg(&src_idx[min(e + eoff, e1 - 1)]);
#pragma unroll
        for (int k = 0; k < 8; ++k) {
            int idx = __shfl_sync(0xffffffffu, my, halfsel + k);
            if (ebase + k < rem) {             // predicated: no wasted loads
                float4 v = __ldg(&src4[(long long)idx * 16 + sub]);
                acc.x += v.x; acc.y += v.y; acc.z += v.z; acc.w += v.w;
            }
        }
    }

    // combine the two halves: lane s += lane s+16
    acc.x += __shfl_down_sync(0xffffffffu, acc.x, 16);
    acc.y += __shfl_down_sync(0xffffffffu, acc.y, 16);
    acc.z += __shfl_down_sync(0xffffffffu, acc.z, 16);
    acc.w += __shfl_down_sync(0xffffffffu, acc.w, 16);

    if (lane < 16) {
        float4* p = (float4*)&out[(long long)node * 64 + sub * 4];
        *p = acc;                              // also zeroes empty nodes
    }
}

extern "C" void kernel_launch(void* const* d_in, const int* in_sizes, int n_in,
                              void* d_out, int out_size) {
    const float* source  = (const float*)d_in[0];
    const int*   src_idx = (const int*)d_in[2];
    const int*   seg_ids = (const int*)d_in[3];
    float* out = (float*)d_out;

    int E = in_sizes[2];
    int n_nodes = out_size / 64;

    // A) per-node edge ranges from sorted seg_ids
    boundary_kernel<<<(E + 255) / 256, 256>>>(seg_ids, E);

    // B) warp-per-node gather + sum (writes every output row)
    gather_kernel<<<(n_nodes + 7) / 8, 256>>>(
        (const float4*)source, src_idx, out, n_nodes);
}

// round 10
// speedup vs baseline: 1.2322x; 1.2322x over previous
#include <cuda_runtime.h>

// out = segment_sum(source[src_idx], seg_ids); softmax over singleton axis==1,
// so all attention machinery is dead code.
//
// Edge-parallel (proven best shape, R4/R5) with two fixes:
//  * persistent single-wave grid: 888 blocks (6/SM at 40 regs), 7104 warps,
//    balanced contiguous partition of 8-edge groups -> no wave-quantization
//    tail (old grid ran 1.76 waves at 6 blocks/SM).
//  * uniform-oct fast path: if all 8 edges share one segment (common at mean
//    degree 16), skip per-edge compares entirely.
// Lane holds 2 cols (float2): warp gather = 256B row; 8 independent gathers
// in flight. Sorted seg_ids: interior segments are exclusively owned by the
// warp's contiguous range -> plain STG; boundary segments -> atomicAdd.
//
// Inputs: 0 source[N,64] f32, 2 src_idx[E] i32, 3 seg_ids[E] i32 (sorted).

#define NBLOCKS 888
#define NTHREADS 256
#define NWARPS (NBLOCKS * (NTHREADS / 32))

__global__ void zero_out_kernel(float4* __restrict__ out4, int n4) {
    int i = blockIdx.x * blockDim.x + threadIdx.x;
    int stride = gridDim.x * blockDim.x;
    for (int j = i; j < n4; j += stride)
        out4[j] = make_float4(0.f, 0.f, 0.f, 0.f);
}

__global__ void __launch_bounds__(NTHREADS)
seg_gather_sum_kernel(const float2* __restrict__ src2,
                      const int4* __restrict__ src_idx4,
                      const int4* __restrict__ seg_ids4,
                      const int* __restrict__ src_idx,
                      const int* __restrict__ seg_ids,
                      float* __restrict__ out,
                      int E) {
    const int lane = threadIdx.x & 31;
    const int warp = blockIdx.x * (NTHREADS / 32) + (threadIdx.x >> 5);

    // balanced partition of 8-edge groups ("octs") across all warps
    const int noct_total = (E + 7) >> 3;
    const int q = noct_total / NWARPS;
    const int r = noct_total - q * NWARPS;
    const int o0 = warp * q + (warp < r ? warp : r);
    const int mycnt = q + (warp < r ? 1 : 0);
    if (mycnt == 0) return;

    int e = o0 << 3;
    int e1 = e + (mycnt << 3);
    if (e1 > E) e1 = E;

    const int first_seg = seg_ids[e];
    int cur = first_seg;
    float ax = 0.f, ay = 0.f;

#define FLUSH()                                                         \
    do {                                                                \
        float2* p = (float2*)&out[(long long)cur * 64 + 2 * lane];      \
        if (cur == first_seg) {                                         \
            atomicAdd(&((float*)p)[0], ax);                             \
            atomicAdd(&((float*)p)[1], ay);                             \
        } else {                                                        \
            *p = make_float2(ax, ay);                                   \
        }                                                               \
        ax = 0.f; ay = 0.f;                                             \
    } while (0)

#define ACC(S, V)                                                       \
    do {                                                                \
        if ((S) != cur) { FLUSH(); cur = (S); }                         \
        ax += (V).x; ay += (V).y;                                       \
    } while (0)

    int noct = (e1 - e) >> 3;
    for (int t = 0; t < noct; ++t, e += 8) {
        int4 sa = __ldg(&seg_ids4[(e >> 2) + 0]);
        int4 sb = __ldg(&seg_ids4[(e >> 2) + 1]);
        int4 ia = __ldg(&src_idx4[(e >> 2) + 0]);
        int4 ib = __ldg(&src_idx4[(e >> 2) + 1]);

        float2 v0 = __ldg(&src2[(long long)ia.x * 32 + lane]);
        float2 v1 = __ldg(&src2[(long long)ia.y * 32 + lane]);
        float2 v2 = __ldg(&src2[(long long)ia.z * 32 + lane]);
        float2 v3 = __ldg(&src2[(long long)ia.w * 32 + lane]);
        float2 v4 = __ldg(&src2[(long long)ib.x * 32 + lane]);
        float2 v5 = __ldg(&src2[(long long)ib.y * 32 + lane]);
        float2 v6 = __ldg(&src2[(long long)ib.z * 32 + lane]);
        float2 v7 = __ldg(&src2[(long long)ib.w * 32 + lane]);

        if (sa.x == sb.w) {
            // whole oct in one segment (common): one compare total
            if (sa.x != cur) { FLUSH(); cur = sa.x; }
            ax += v0.x + v1.x + v2.x + v3.x + v4.x + v5.x + v6.x + v7.x;
            ay += v0.y + v1.y + v2.y + v3.y + v4.y + v5.y + v6.y + v7.y;
        } else {
            ACC(sa.x, v0);
            ACC(sa.y, v1);
            ACC(sa.z, v2);
            ACC(sa.w, v3);
            ACC(sb.x, v4);
            ACC(sb.y, v5);
            ACC(sb.z, v6);
            ACC(sb.w, v7);
        }
    }

    // tail (E % 8 != 0 only in the last warp's range)
    for (; e < e1; ++e) {
        int s = __ldg(&seg_ids[e]);
        int idx = __ldg(&src_idx[e]);
        float2 v = __ldg(&src2[(long long)idx * 32 + lane]);
        ACC(s, v);
    }
#undef ACC
#undef FLUSH

    // running segment may continue into the next warp's range -> atomic
    atomicAdd(&out[(long long)cur * 64 + 2 * lane + 0], ax);
    atomicAdd(&out[(long long)cur * 64 + 2 * lane + 1], ay);
}

extern "C" void kernel_launch(void* const* d_in, const int* in_sizes, int n_in,
                              void* d_out, int out_size) {
    const float* source  = (const float*)d_in[0];
    const int*   src_idx = (const int*)d_in[2];
    const int*   seg_ids = (const int*)d_in[3];
    float* out = (float*)d_out;

    int E = in_sizes[2];

    // 1) zero the output (poisoned; empty segments must be 0)
    int n4 = out_size / 4;
    zero_out_kernel<<<NBLOCKS, NTHREADS>>>((float4*)d_out, n4);

    // 2) gather + segment-sum, persistent single wave
    seg_gather_sum_kernel<<<NBLOCKS, NTHREADS>>>(
        (const float2*)source, (const int4*)src_idx, (const int4*)seg_ids,
        src_idx, seg_ids, out, E);
}